// round 2
// baseline (speedup 1.0000x reference)
#include <cuda_runtime.h>
#include <cstdint>

#define DIMD 256
#define NEMB 512
#define TM 128
#define AS_STRIDE 132   // 132*4B row stride: 16B-aligned rows, low STS conflict

__device__ __align__(16) float  g_EN [NEMB * DIMD];   // normalized codebook [j][d]
__device__ __align__(16) float  g_ENT[DIMD * NEMB];   // transposed         [d][j]
__device__ __align__(16) float  g_C  [NEMB];          // c_j = sum(e_hat^2)
__device__ double g_entropy;
__device__ double g_partials[2048];

// ---------------- Phase A1: normalize codebook rows ----------------
__global__ void k_norm(const float* __restrict__ emb) {
    int j = blockIdx.x;      // 0..511
    int t = threadIdx.x;     // 0..63
    __shared__ float red[64];
    float4 v = reinterpret_cast<const float4*>(emb + j * DIMD)[t];
    red[t] = v.x * v.x + v.y * v.y + v.z * v.z + v.w * v.w;
    __syncthreads();
    for (int o = 32; o > 0; o >>= 1) { if (t < o) red[t] += red[t + o]; __syncthreads(); }
    float nrm = sqrtf(red[0]);
    __syncthreads();
    float4 q;
    q.x = v.x / nrm; q.y = v.y / nrm; q.z = v.z / nrm; q.w = v.w / nrm;
    reinterpret_cast<float4*>(g_EN + j * DIMD)[t] = q;
    int d = t * 4;
    g_ENT[(d + 0) * NEMB + j] = q.x;
    g_ENT[(d + 1) * NEMB + j] = q.y;
    g_ENT[(d + 2) * NEMB + j] = q.z;
    g_ENT[(d + 3) * NEMB + j] = q.w;
    red[t] = q.x * q.x + q.y * q.y + q.z * q.z + q.w * q.w;
    __syncthreads();
    for (int o = 32; o > 0; o >>= 1) { if (t < o) red[t] += red[t + o]; __syncthreads(); }
    if (t == 0) g_C[j] = red[0];
}

// ---------------- Phase A2: entropy = 2E*sum(c) - 2*||sum_j e_hat_j||^2 ----
__global__ void k_entropy() {
    int t = threadIdx.x;  // 256
    float s = 0.f;
    for (int j = 0; j < NEMB; j++) s += g_EN[j * DIMD + t];
    double val = 2.0 * (double)NEMB * ((double)g_C[t] + (double)g_C[t + 256])
               - 2.0 * (double)s * (double)s;
    __shared__ double red[256];
    red[t] = val; __syncthreads();
    for (int o = 128; o > 0; o >>= 1) { if (t < o) red[t] += red[t + o]; __syncthreads(); }
    if (t == 0) g_entropy = red[0];
}

// ---------------- packed f32x2 helpers (Blackwell FFMA2 path) ----------------
__device__ __forceinline__ unsigned long long pack2(float a) {
    unsigned long long r;
    asm("mov.b64 %0, {%1, %1};" : "=l"(r) : "f"(a));
    return r;
}
__device__ __forceinline__ void fma2(unsigned long long& c, unsigned long long a,
                                     unsigned long long b) {
    asm("fma.rn.f32x2 %0, %1, %2, %0;" : "+l"(c) : "l"(a), "l"(b));
}

#define CP16(dst, src) asm volatile("cp.async.cg.shared.global [%0], [%1], 16;" :: "r"(dst), "l"(src))
#define CP_COMMIT()    asm volatile("cp.async.commit_group;")
#define CP_WAIT(n)     asm volatile("cp.async.wait_group %0;" :: "n"(n))

__device__ __forceinline__ void prefetchB(float* BsBuf, int j0, int kbase, int tid) {
#pragma unroll
    for (int i = 0; i < 2; i++) {
        int idx = tid + i * 256;
        int k   = idx >> 5;     // 0..15
        int j4  = idx & 31;     // 0..31
        const float* src = g_ENT + (size_t)(kbase + k) * NEMB + j0 + j4 * 4;
        unsigned dst = (unsigned)__cvta_generic_to_shared(BsBuf + k * 128 + j4 * 4);
        CP16(dst, src);
    }
}

// ---------------- Main: fused GEMM + argmin + gather + diff ----------------
__global__ void __launch_bounds__(256, 1) k_main(
        const float* __restrict__ input,
        float* __restrict__ out,
        float* __restrict__ ind_out)
{
    extern __shared__ float smem[];
    float*  As   = smem;                      // [256][AS_STRIDE] k-major A tile
    float*  Bs   = smem + DIMD * AS_STRIDE;   // [2][16][128] double-buffered B
    float*  sc   = Bs + 2 * 16 * 128;         // [512] c_j cache
    int*    sInd = (int*)(sc + NEMB);         // [128]
    float*  sSq  = (float*)(sInd + TM);       // [128] fp32 row-norm^2 (ref scale)
    double* dred = (double*)(sSq + TM);       // [256]

    const int  tid = threadIdx.x;
    const long r0  = (long)blockIdx.x * TM;
    const int  w = tid >> 5, l = tid & 31;
    const int  r2 = l & 7, c2 = l >> 3;

    for (int i = tid; i < NEMB; i += 256) sc[i] = g_C[i];

    // load + transpose A into smem (k-major), 2-way STS conflicts only
#pragma unroll
    for (int itr = 0; itr < 2; itr++)
#pragma unroll 4
        for (int itc = 0; itc < 16; itc++) {
            int row = w * 8 + r2 + itr * 64;
            int c4  = itc * 4 + c2;
            float4 v = *reinterpret_cast<const float4*>(input + (r0 + row) * DIMD + c4 * 4);
            int k = c4 * 4;
            As[(k + 0) * AS_STRIDE + row] = v.x;
            As[(k + 1) * AS_STRIDE + row] = v.y;
            As[(k + 2) * AS_STRIDE + row] = v.z;
            As[(k + 3) * AS_STRIDE + row] = v.w;
        }

    const int tx = tid & 15, ty = tid >> 4;

    float bestS[8];
    int   bestI[8];
#pragma unroll
    for (int i = 0; i < 8; i++) { bestS[i] = 3.0e38f; bestI[i] = 0; }

    __syncthreads();  // As + sc visible

    // ---- per-row ||x||^2 in double, rounded to fp32 (matches ref dist scale)
    {
        int row  = tid & 127;
        int half = tid >> 7;                  // 0 or 1
        const float* Ar = As + row + half * 128 * AS_STRIDE;
        double acc = 0.0;
#pragma unroll 8
        for (int k = 0; k < 128; k++) {
            double a = (double)Ar[k * AS_STRIDE];
            acc += a * a;
        }
        dred[tid] = acc;
    }
    __syncthreads();
    if (tid < TM) sSq[tid] = (float)(dred[tid] + dred[tid + 128]);
    __syncthreads();

    for (int jt = 0; jt < 4; jt++) {
        const int j0 = jt * 128;
        unsigned long long acc[8][4];
#pragma unroll
        for (int i = 0; i < 8; i++)
#pragma unroll
            for (int jj = 0; jj < 4; jj++) acc[i][jj] = 0ULL;

        prefetchB(Bs, j0, 0, tid);
        CP_COMMIT();

        for (int kt = 0; kt < 16; kt++) {
            if (kt < 15) {
                prefetchB(Bs + ((kt + 1) & 1) * 2048, j0, (kt + 1) * 16, tid);
                CP_COMMIT();
                CP_WAIT(1);
            } else {
                CP_WAIT(0);
            }
            __syncthreads();
            const float* Bc = Bs + (kt & 1) * 2048;
            const float* Ak = As + kt * 16 * AS_STRIDE;
#pragma unroll
            for (int kk = 0; kk < 16; kk++) {
                float4 a0 = *reinterpret_cast<const float4*>(Ak + kk * AS_STRIDE + ty * 8);
                float4 a1 = *reinterpret_cast<const float4*>(Ak + kk * AS_STRIDE + ty * 8 + 4);
                ulonglong2 b01 = *reinterpret_cast<const ulonglong2*>(Bc + kk * 128 + tx * 8);
                ulonglong2 b23 = *reinterpret_cast<const ulonglong2*>(Bc + kk * 128 + tx * 8 + 4);
                const unsigned long long bp0 = b01.x, bp1 = b01.y, bp2 = b23.x, bp3 = b23.y;
                float av[8] = {a0.x, a0.y, a0.z, a0.w, a1.x, a1.y, a1.z, a1.w};
#pragma unroll
                for (int i = 0; i < 8; i++) {
                    unsigned long long ap = pack2(av[i]);
                    fma2(acc[i][0], ap, bp0);
                    fma2(acc[i][1], ap, bp1);
                    fma2(acc[i][2], ap, bp2);
                    fma2(acc[i][3], ap, bp3);
                }
            }
            __syncthreads();
        }

        // fold this j-tile into running argmin, replicating the reference's
        // fp32 rounding: dist = fl( fl(sq - fl(2*dot)) + c_j )  (no FMA fusion)
#pragma unroll
        for (int i = 0; i < 8; i++) {
            float sqr = sSq[ty * 8 + i];
#pragma unroll
            for (int jj = 0; jj < 4; jj++) {
                float2 d = *reinterpret_cast<float2*>(&acc[i][jj]);
                int j = j0 + tx * 8 + jj * 2;
                float s0 = __fadd_rn(__fsub_rn(sqr, __fmul_rn(2.0f, d.x)), sc[j]);
                float s1 = __fadd_rn(__fsub_rn(sqr, __fmul_rn(2.0f, d.y)), sc[j + 1]);
                if (s0 < bestS[i]) { bestS[i] = s0; bestI[i] = j; }
                if (s1 < bestS[i]) { bestS[i] = s1; bestI[i] = j + 1; }
            }
        }
    }

    // cross-thread argmin over the 16-lane row group (xor<16 stays in half-warp)
    const unsigned mask = 0xFFFFFFFFu;
#pragma unroll
    for (int i = 0; i < 8; i++) {
        float s = bestS[i]; int bi = bestI[i];
#pragma unroll
        for (int o = 8; o > 0; o >>= 1) {
            float so = __shfl_xor_sync(mask, s, o);
            int   io = __shfl_xor_sync(mask, bi, o);
            if (so < s || (so == s && io < bi)) { s = so; bi = io; }
        }
        bestS[i] = s; bestI[i] = bi;
    }
    if (tx == 0) {
#pragma unroll
        for (int i = 0; i < 8; i++) {
            int r = ty * 8 + i;
            sInd[r] = bestI[i];
            ind_out[r0 + r] = (float)bestI[i];
        }
    }
    __syncthreads();

    // gather normalized codes -> out, accumulate sum((q-x)^2)
    float fsum = 0.f;
#pragma unroll
    for (int itr = 0; itr < 2; itr++)
        for (int itc = 0; itc < 16; itc++) {
            int row = w * 8 + r2 + itr * 64;
            int c4  = itc * 4 + c2;
            int jb  = sInd[row];
            float4 q = *reinterpret_cast<const float4*>(g_EN + jb * DIMD + c4 * 4);
            float4 x = *reinterpret_cast<const float4*>(input + (r0 + row) * DIMD + c4 * 4);
            *reinterpret_cast<float4*>(out + (r0 + row) * DIMD + c4 * 4) = q;
            float dx = q.x - x.x, dy = q.y - x.y, dz = q.z - x.z, dw = q.w - x.w;
            fsum += dx * dx + dy * dy + dz * dz + dw * dw;
        }

    dred[tid] = (double)fsum;
    __syncthreads();
    for (int o = 128; o > 0; o >>= 1) { if (tid < o) dred[tid] += dred[tid + o]; __syncthreads(); }
    if (tid == 0) g_partials[blockIdx.x] = dred[0];
}

// ---------------- final: loss = diff - entropy/E^2 ----------------
__global__ void k_final(float* __restrict__ loss_out, int nblocks, long n) {
    __shared__ double red[256];
    int t = threadIdx.x;
    double s = 0.0;
    for (int i = t; i < nblocks; i += 256) s += g_partials[i];
    red[t] = s; __syncthreads();
    for (int o = 128; o > 0; o >>= 1) { if (t < o) red[t] += red[t + o]; __syncthreads(); }
    if (t == 0) {
        double diff = red[0] / (double)n;
        double loss = diff - g_entropy / ((double)NEMB * (double)NEMB);
        loss_out[0] = (float)loss;
    }
}

extern "C" void kernel_launch(void* const* d_in, const int* in_sizes, int n_in,
                              void* d_out, int out_size) {
    const float* input = (const float*)d_in[0];
    const float* emb   = (const float*)d_in[1];
    long n      = (long)in_sizes[0];       // B*T*D = 33554432
    int  nrows  = (int)(n / DIMD);         // 131072
    int  nblk   = nrows / TM;              // 1024
    float* out    = (float*)d_out;
    float* loss_p = out + n;               // layout: [out | loss | embed_ind]
    float* ind_p  = out + n + 1;

    size_t smem = (size_t)(DIMD * AS_STRIDE + 2 * 16 * 128 + NEMB) * sizeof(float)
                + TM * sizeof(int) + TM * sizeof(float) + 256 * sizeof(double);
    cudaFuncSetAttribute(k_main, cudaFuncAttributeMaxDynamicSharedMemorySize, (int)smem);

    k_norm   <<<NEMB, 64>>>(emb);
    k_entropy<<<1, 256>>>();
    k_main   <<<nblk, 256, smem>>>(input, out, ind_p);
    k_final  <<<1, 256>>>(loss_p, nblk, n);
}